// round 15
// baseline (speedup 1.0000x reference)
#include <cuda_runtime.h>
#include <cuda_bf16.h>
#include <stdint.h>
#include <math.h>

#define Bn   8
#define Cn   256
#define Hn   64
#define Wn   64
#define Pn   4096
#define SCALEF 0.1767766952966369f

// qkv quad-interleaved: [b][g=s*8+hd :24][dq:8][p:4096][4] fp32
__device__ float g_qkv[(size_t)Bn * 24 * Pn * 32];
__device__ __nv_bfloat16 g_w1[768 * 768];              // [Whi|Wlo|Whi] along K
__device__ __nv_bfloat16 g_w2[256 * 768];
__device__ __nv_bfloat16 g_xhi[(size_t)Bn * Pn * Cn];  // [b][p][c]
__device__ __nv_bfloat16 g_xlo[(size_t)Bn * Pn * Cn];
__device__ __nv_bfloat16 g_ahi[(size_t)Bn * Pn * Cn];
__device__ __nv_bfloat16 g_alo[(size_t)Bn * Pn * Cn];

// ---------------- helpers ----------------
__device__ __forceinline__ uint32_t s2u(const void* p) {
    uint32_t a;
    asm("{ .reg .u64 t; cvta.to.shared.u64 t, %1; cvt.u32.u64 %0, t; }" : "=r"(a) : "l"(p));
    return a;
}
__device__ __forceinline__ void cp16(uint32_t dst, const void* src) {
    asm volatile("cp.async.cg.shared.global [%0], [%1], 16;" :: "r"(dst), "l"(src));
}
#define CP_COMMIT() asm volatile("cp.async.commit_group;" ::: "memory")
#define CP_WAIT(n)  asm volatile("cp.async.wait_group %0;" :: "n"(n) : "memory")
#define SWZ(o) ((o) ^ (((o) >> 3) & 0x70))

__device__ __forceinline__ void ldsm4(uint32_t* r, uint32_t a) {
    asm volatile("ldmatrix.sync.aligned.m8n8.x4.shared.b16 {%0,%1,%2,%3}, [%4];"
                 : "=r"(r[0]), "=r"(r[1]), "=r"(r[2]), "=r"(r[3]) : "r"(a));
}
__device__ __forceinline__ void mma16816(float* c, const uint32_t* a, uint32_t b0, uint32_t b1) {
    asm volatile("mma.sync.aligned.m16n8k16.row.col.f32.bf16.bf16.f32 "
                 "{%0,%1,%2,%3},{%4,%5,%6,%7},{%8,%9},{%0,%1,%2,%3};"
                 : "+f"(c[0]), "+f"(c[1]), "+f"(c[2]), "+f"(c[3])
                 : "r"(a[0]), "r"(a[1]), "r"(a[2]), "r"(a[3]), "r"(b0), "r"(b1));
}

// ---------------- prep: weight hi/lo concat ----------------
__global__ void prep_w1(const float* __restrict__ wq) {
    int idx = blockIdx.x * 256 + threadIdx.x;
    if (idx < 768 * 768) {
        int m = idx / 768, k = idx % 768;
        float v = wq[m * 256 + (k & 255)];
        __nv_bfloat16 h = __float2bfloat16(v);
        if (k >= 256 && k < 512) h = __float2bfloat16(v - __bfloat162float(__float2bfloat16(v)));
        g_w1[idx] = h;
    }
}
__global__ void prep_w2(const float* __restrict__ wp) {
    int idx = blockIdx.x * 256 + threadIdx.x;
    if (idx < 256 * 768) {
        int m = idx / 768, k = idx % 768;
        float v = wp[m * 256 + (k & 255)];
        __nv_bfloat16 h = __float2bfloat16(v);
        if (k >= 256 && k < 512) h = __float2bfloat16(v - __bfloat162float(__float2bfloat16(v)));
        g_w2[idx] = h;
    }
}

// -------- transpose + hi/lo split: [b][c][p] fp32 -> [b][p][c] bf16 x2 --------
__global__ void conv_split(const float* __restrict__ in,
                           __nv_bfloat16* __restrict__ ohi,
                           __nv_bfloat16* __restrict__ olo) {
    __shared__ float t[32][33];
    const int b = blockIdx.z, c0 = blockIdx.y * 32, p0 = blockIdx.x * 32;
    const int tx = threadIdx.x, ty = threadIdx.y;
    const float* ip = in + ((size_t)b * Cn + c0) * Pn + p0;
#pragma unroll
    for (int r = 0; r < 4; r++)
        t[ty + r * 8][tx] = ip[(size_t)(ty + r * 8) * Pn + tx];
    __syncthreads();
#pragma unroll
    for (int r = 0; r < 4; r++) {
        int pr = ty + r * 8;
        float v = t[tx][pr];
        __nv_bfloat16 h = __float2bfloat16(v);
        __nv_bfloat16 l = __float2bfloat16(v - __bfloat162float(h));
        size_t o = ((size_t)b * Pn + p0 + pr) * Cn + c0 + tx;
        ohi[o] = h; olo[o] = l;
    }
}

// ---------------- HMMA bf16 GEMM (R11 config: 128x64 tile, 3 CTA/SM) ----------------
template <int LAYOUT>
__global__ void __launch_bounds__(128, 3) hmma_gemm(const __nv_bfloat16* __restrict__ A,
                                                    const __nv_bfloat16* __restrict__ Bhi,
                                                    const __nv_bfloat16* __restrict__ Blo,
                                                    const float* __restrict__ bias,
                                                    float* __restrict__ Out,
                                                    int boff) {
    extern __shared__ char smraw[];
    const uint32_t sbr = s2u(smraw);
    const uint32_t sb = (sbr + 1023u) & ~1023u;
    char* smg = smraw + (sb - sbr);

    const int t = threadIdx.x, lane = t & 31, wid = t >> 5;
    const int b = blockIdx.z + boff, m0 = blockIdx.y * 128, n0 = blockIdx.x * 64;
    const int wm = wid >> 1, wn = wid & 1;          // 2x2 warps, 64x32 each

    const uint32_t sA = sb;              // 3 x 16KB A stage buffers
    const uint32_t sB = sb + 49152;      // 3 x 8KB B stage buffers

    auto load_A = [&](int ac, int buf) {
        const __nv_bfloat16* asrc = A + (size_t)m0 * 768 + ac * 64;
        const uint32_t ab = sA + buf * 16384;
#pragma unroll
        for (int i = 0; i < 8; i++) {
            int u = t + i * 128, row = u >> 3, ch = u & 7;
            uint32_t off = row * 128 + ch * 16;
            cp16(ab + SWZ(off), asrc + (size_t)row * 768 + ch * 8);
        }
    };
    auto load_B = [&](int bi, int buf) {
        const __nv_bfloat16* bsrc = ((bi < 4) ? Bhi : Blo) + ((size_t)(b * Pn + n0)) * 256 + (bi & 3) * 64;
        const uint32_t bb = sB + buf * 8192;
#pragma unroll
        for (int i = 0; i < 4; i++) {
            int u = t + i * 128, row = u >> 3, ch = u & 7;
            uint32_t off = row * 128 + ch * 16;
            cp16(bb + SWZ(off), bsrc + (size_t)row * 256 + ch * 8);
        }
    };
    auto a_of = [](int s) { return s < 8 ? ((s & 1) * 4 + (s >> 1)) : s; };
    auto b_of = [](int s) { return s < 8 ? (s >> 1) : (s - 4); };

    float acc[4][4][4] = {};

    load_A(a_of(0), 0); load_B(b_of(0), 0); CP_COMMIT();
    load_A(a_of(1), 1); CP_COMMIT();   // stage 1 shares B tile 0

    for (int s = 0; s < 12; s++) {
        if (s == 11) { CP_WAIT(0); } else { CP_WAIT(1); }
        __syncthreads();
        const uint32_t abase = sA + (s % 3) * 16384;
        const uint32_t bbase = sB + (b_of(s) % 3) * 8192;
#pragma unroll
        for (int kk = 0; kk < 4; kk++) {
            uint32_t af[4][4], bf[2][4];
#pragma unroll
            for (int mf = 0; mf < 4; mf++) {
                uint32_t off = (uint32_t)(wm * 64 + mf * 16 + (lane & 15)) * 128
                             + kk * 32 + ((lane >> 4) << 4);
                ldsm4(af[mf], abase + SWZ(off));
            }
#pragma unroll
            for (int np = 0; np < 2; np++) {
                uint32_t off = (uint32_t)(wn * 32 + np * 16 + (lane & 7) + ((lane >> 4) << 3)) * 128
                             + kk * 32 + (((lane >> 3) & 1) << 4);
                ldsm4(bf[np], bbase + SWZ(off));
            }
#pragma unroll
            for (int mf = 0; mf < 4; mf++)
#pragma unroll
                for (int nf = 0; nf < 4; nf++)
                    mma16816(acc[mf][nf], af[mf], bf[nf >> 1][(nf & 1) * 2], bf[nf >> 1][(nf & 1) * 2 + 1]);
        }
        if (s + 2 < 12) {
            const int sp = s + 2;
            load_A(a_of(sp), sp % 3);
            if (b_of(sp) != b_of(sp - 1))
                load_B(b_of(sp), b_of(sp) % 3);
            CP_COMMIT();
        }
    }

    if (LAYOUT == 0) {
        __syncthreads();
        float* patch = (float*)smg + wid * (64 * 33);
#pragma unroll
        for (int mf = 0; mf < 4; mf++) {
            const int r0 = mf * 16 + (lane >> 2);
#pragma unroll
            for (int nf = 0; nf < 4; nf++) {
                const int cb = nf * 8 + 2 * (lane & 3);
                patch[r0 * 33 + cb]           = acc[mf][nf][0];
                patch[r0 * 33 + cb + 1]       = acc[mf][nf][1];
                patch[(r0 + 8) * 33 + cb]     = acc[mf][nf][2];
                patch[(r0 + 8) * 33 + cb + 1] = acc[mf][nf][3];
            }
        }
        __syncwarp();
        const int p = n0 + wn * 32 + lane;
#pragma unroll
        for (int q = 0; q < 16; q++) {
            const int mg = m0 + wm * 64 + q * 4;
            float4 v = make_float4(patch[(q * 4 + 0) * 33 + lane] + bias[mg],
                                   patch[(q * 4 + 1) * 33 + lane] + bias[mg + 1],
                                   patch[(q * 4 + 2) * 33 + lane] + bias[mg + 2],
                                   patch[(q * 4 + 3) * 33 + lane] + bias[mg + 3]);
            const int g = mg >> 5, dq = (mg & 31) >> 2;
            *(float4*)(Out + (((size_t)(b * 24 + g) * 8 + dq) * Pn + p) * 4) = v;
        }
    } else {
#pragma unroll
        for (int mf = 0; mf < 4; mf++) {
            const int r0 = m0 + wm * 64 + mf * 16 + (lane >> 2);
            const float b0v = bias[r0], b1v = bias[r0 + 8];
#pragma unroll
            for (int nf = 0; nf < 4; nf++) {
                const int cc = n0 + wn * 32 + nf * 8 + 2 * (lane & 3);
                float2 v0 = make_float2(acc[mf][nf][0] + b0v, acc[mf][nf][1] + b0v);
                *(float2*)(Out + ((size_t)b * 256 + r0) * Pn + cc) = v0;
                float2 v1 = make_float2(acc[mf][nf][2] + b1v, acc[mf][nf][3] + b1v);
                *(float2*)(Out + ((size_t)b * 256 + r0 + 8) * Pn + cc) = v1;
            }
        }
    }
}

// ---------------- warp-cooperative attention (R11, + batch offset) ----------------
__global__ void __launch_bounds__(128) attn_kernel(int boff) {
    const int bh = blockIdx.y + boff * 8;
    const int b  = bh >> 3;
    const int hd = bh & 7;
    const int lane = threadIdx.x & 31, warp = threadIdx.x >> 5;
    const int plocal = lane & 7, sub = lane >> 3;
    const int p  = blockIdx.x * 32 + warp * 8 + plocal;
    const int h  = p >> 6;
    const int w  = p & 63;
    const int dil = (hd & 3) + 1;

    const float* qb = g_qkv + ((size_t)((b * 24 + 0 * 8 + hd) * 8)) * Pn * 4;
    const float* kb = g_qkv + ((size_t)((b * 24 + 1 * 8 + hd) * 8)) * Pn * 4;
    const float* vb = g_qkv + ((size_t)((b * 24 + 2 * 8 + hd) * 8)) * Pn * 4;

    const int dq0 = 2 * sub, dq1 = 2 * sub + 1;
    const float4 q0 = *(const float4*)(qb + ((size_t)dq0 * Pn + p) * 4);
    const float4 q1 = *(const float4*)(qb + ((size_t)dq1 * Pn + p) * 4);

    float s[9];
    int   np[9];
#pragma unroll
    for (int dy = 0; dy < 3; dy++) {
#pragma unroll
        for (int dx = 0; dx < 3; dx++) {
            const int j  = dy * 3 + dx;
            const int hh = h + (dy - 1) * dil;
            const int ww = w + (dx - 1) * dil;
            const bool valid = (hh >= 0 && hh < Hn && ww >= 0 && ww < Wn);
            const int pn = valid ? (hh * Wn + ww) : p;
            float4 k0 = *(const float4*)(kb + ((size_t)dq0 * Pn + pn) * 4);
            float4 k1 = *(const float4*)(kb + ((size_t)dq1 * Pn + pn) * 4);
            float part = q0.x * k0.x + q0.y * k0.y + q0.z * k0.z + q0.w * k0.w
                       + q1.x * k1.x + q1.y * k1.y + q1.z * k1.z + q1.w * k1.w;
            part += __shfl_xor_sync(0xFFFFFFFFu, part, 8);
            part += __shfl_xor_sync(0xFFFFFFFFu, part, 16);
            s[j]  = valid ? part * SCALEF : 0.f;
            np[j] = valid ? pn : -1;
        }
    }

    float mx = s[0];
#pragma unroll
    for (int j = 1; j < 9; j++) mx = fmaxf(mx, s[j]);
    float e[9];
    float sum = 0.f;
#pragma unroll
    for (int j = 0; j < 9; j++) { e[j] = __expf(s[j] - mx); sum += e[j]; }
    const float inv = 1.f / sum;

    float o0x = 0.f, o0y = 0.f, o0z = 0.f, o0w = 0.f;
    float o1x = 0.f, o1y = 0.f, o1z = 0.f, o1w = 0.f;
#pragma unroll
    for (int j = 0; j < 9; j++) {
        if (np[j] >= 0) {
            const float ej = e[j];
            float4 v0 = *(const float4*)(vb + ((size_t)dq0 * Pn + np[j]) * 4);
            float4 v1 = *(const float4*)(vb + ((size_t)dq1 * Pn + np[j]) * 4);
            o0x += ej * v0.x; o0y += ej * v0.y; o0z += ej * v0.z; o0w += ej * v0.w;
            o1x += ej * v1.x; o1y += ej * v1.y; o1z += ej * v1.z; o1w += ej * v1.w;
        }
    }
    o0x *= inv; o0y *= inv; o0z *= inv; o0w *= inv;
    o1x *= inv; o1y *= inv; o1z *= inv; o1w *= inv;

    float ov[8] = {o0x, o0y, o0z, o0w, o1x, o1y, o1z, o1w};
    uint32_t hw[4], lw[4];
#pragma unroll
    for (int j = 0; j < 4; j++) {
        float f0 = ov[2 * j], f1 = ov[2 * j + 1];
        __nv_bfloat162 h2 = __floats2bfloat162_rn(f0, f1);
        float r0 = f0 - __bfloat162float(h2.x);
        float r1 = f1 - __bfloat162float(h2.y);
        __nv_bfloat162 l2 = __floats2bfloat162_rn(r0, r1);
        hw[j] = *(uint32_t*)&h2;
        lw[j] = *(uint32_t*)&l2;
    }
    const size_t co = ((size_t)(b * Pn + p)) * 256 + hd * 32 + sub * 8;
    *(uint4*)(g_ahi + co) = make_uint4(hw[0], hw[1], hw[2], hw[3]);
    *(uint4*)(g_alo + co) = make_uint4(lw[0], lw[1], lw[2], lw[3]);
}

// ---------------------------------------------------------------------------
// Batch-chunked pipeline: gemm0 chunks stream on the origin stream; each
// chunk's attn+gemm1 run on a forked stream underneath the next gemm0 chunk.
extern "C" void kernel_launch(void* const* d_in, const int* in_sizes, int n_in,
                              void* d_out, int out_size) {
    const float* x      = (const float*)d_in[0];
    const float* w_qkv  = (const float*)d_in[1];
    const float* b_qkv  = (const float*)d_in[2];
    const float* w_proj = (const float*)d_in[3];
    const float* b_proj = (const float*)d_in[4];
    float* out = (float*)d_out;

    float* qkvp = nullptr;
    __nv_bfloat16 *w1p = nullptr, *w2p = nullptr, *xhip = nullptr, *xlop = nullptr,
                  *ahip = nullptr, *alop = nullptr;
    cudaGetSymbolAddress((void**)&qkvp, g_qkv);
    cudaGetSymbolAddress((void**)&w1p, g_w1);
    cudaGetSymbolAddress((void**)&w2p, g_w2);
    cudaGetSymbolAddress((void**)&xhip, g_xhi);
    cudaGetSymbolAddress((void**)&xlop, g_xlo);
    cudaGetSymbolAddress((void**)&ahip, g_ahi);
    cudaGetSymbolAddress((void**)&alop, g_alo);

    const int SMEM_BYTES = 1024 + 49152 + 24576;   // pad + 3x16KB A + 3x8KB B
    cudaFuncSetAttribute(hmma_gemm<0>, cudaFuncAttributeMaxDynamicSharedMemorySize, SMEM_BYTES);
    cudaFuncSetAttribute(hmma_gemm<1>, cudaFuncAttributeMaxDynamicSharedMemorySize, SMEM_BYTES);

    // fork-join stream + events (created per call; kernel_launch runs only a
    // handful of times — correctness + capture — so no meaningful leak)
    cudaStream_t s2;
    cudaStreamCreateWithFlags(&s2, cudaStreamNonBlocking);
    cudaEvent_t ev[4], evJ;
    for (int i = 0; i < 4; i++) cudaEventCreateWithFlags(&ev[i], cudaEventDisableTiming);
    cudaEventCreateWithFlags(&evJ, cudaEventDisableTiming);

    prep_w1<<<(768 * 768 + 255) / 256, 256>>>(w_qkv);
    prep_w2<<<(256 * 768 + 255) / 256, 256>>>(w_proj);
    conv_split<<<dim3(Pn / 32, Cn / 32, Bn), dim3(32, 8)>>>(x, xhip, xlop);

    for (int c = 0; c < 4; c++) {
        const int boff = c * 2;   // 2 batches per chunk
        hmma_gemm<0><<<dim3(Pn / 64, 768 / 128, 2), 128, SMEM_BYTES>>>(
            w1p, xhip, xlop, b_qkv, qkvp, boff);
        cudaEventRecord(ev[c], 0);
        cudaStreamWaitEvent(s2, ev[c], 0);
        attn_kernel<<<dim3(Pn / 32, 16), 128, 0, s2>>>(boff);
        hmma_gemm<1><<<dim3(Pn / 64, 256 / 128, 2), 128, SMEM_BYTES, s2>>>(
            w2p, ahip, alop, b_proj, out, boff);
    }
    cudaEventRecord(evJ, s2);
    cudaStreamWaitEvent(0, evJ, 0);
}

// round 16
// speedup vs baseline: 1.7609x; 1.7609x over previous
#include <cuda_runtime.h>
#include <cuda_fp16.h>
#include <stdint.h>
#include <math.h>

#define Bn   8
#define Cn   256
#define Hn   64
#define Wn   64
#define Pn   4096
#define SCALEF 0.1767766952966369f

// qkv quad-interleaved: [b][g=s*8+hd :24][dq:8][p:4096][4] fp32
__device__ float g_qkv[(size_t)Bn * 24 * Pn * 32];
__device__ __half g_w1[768 * 256];                 // fp16 weights, K=256
__device__ __half g_w2[256 * 256];
__device__ __half g_x[(size_t)Bn * Pn * Cn];       // [b][p][c] fp16
__device__ __half g_a[(size_t)Bn * Pn * Cn];

// ---------------- helpers ----------------
__device__ __forceinline__ uint32_t s2u(const void* p) {
    uint32_t a;
    asm("{ .reg .u64 t; cvta.to.shared.u64 t, %1; cvt.u32.u64 %0, t; }" : "=r"(a) : "l"(p));
    return a;
}
__device__ __forceinline__ void cp16(uint32_t dst, const void* src) {
    asm volatile("cp.async.cg.shared.global [%0], [%1], 16;" :: "r"(dst), "l"(src));
}
#define CP_COMMIT() asm volatile("cp.async.commit_group;" ::: "memory")
#define CP_WAIT(n)  asm volatile("cp.async.wait_group %0;" :: "n"(n) : "memory")
#define SWZ(o) ((o) ^ (((o) >> 3) & 0x70))

__device__ __forceinline__ void ldsm4(uint32_t* r, uint32_t a) {
    asm volatile("ldmatrix.sync.aligned.m8n8.x4.shared.b16 {%0,%1,%2,%3}, [%4];"
                 : "=r"(r[0]), "=r"(r[1]), "=r"(r[2]), "=r"(r[3]) : "r"(a));
}
// f16 inputs, f32 accumulate
__device__ __forceinline__ void mma16816(float* c, const uint32_t* a, uint32_t b0, uint32_t b1) {
    asm volatile("mma.sync.aligned.m16n8k16.row.col.f32.f16.f16.f32 "
                 "{%0,%1,%2,%3},{%4,%5,%6,%7},{%8,%9},{%0,%1,%2,%3};"
                 : "+f"(c[0]), "+f"(c[1]), "+f"(c[2]), "+f"(c[3])
                 : "r"(a[0]), "r"(a[1]), "r"(a[2]), "r"(a[3]), "r"(b0), "r"(b1));
}

// ---------------- prep: weights -> fp16 ----------------
__global__ void prep_w1(const float* __restrict__ wq) {
    int idx = blockIdx.x * 256 + threadIdx.x;
    if (idx < 768 * 256) g_w1[idx] = __float2half(wq[idx]);
}
__global__ void prep_w2(const float* __restrict__ wp) {
    int idx = blockIdx.x * 256 + threadIdx.x;
    if (idx < 256 * 256) g_w2[idx] = __float2half(wp[idx]);
}

// -------- transpose: [b][c][p] fp32 -> [b][p][c] fp16 --------
__global__ void conv_split(const float* __restrict__ in, __half* __restrict__ o16) {
    __shared__ float t[32][33];
    const int b = blockIdx.z, c0 = blockIdx.y * 32, p0 = blockIdx.x * 32;
    const int tx = threadIdx.x, ty = threadIdx.y;
    const float* ip = in + ((size_t)b * Cn + c0) * Pn + p0;
#pragma unroll
    for (int r = 0; r < 4; r++)
        t[ty + r * 8][tx] = ip[(size_t)(ty + r * 8) * Pn + tx];
    __syncthreads();
#pragma unroll
    for (int r = 0; r < 4; r++) {
        int pr = ty + r * 8;
        o16[((size_t)b * Pn + p0 + pr) * Cn + c0 + tx] = __float2half(t[tx][pr]);
    }
}

// ---------------- HMMA fp16 GEMM, single-term K=256 (R11 tile config) ----------------
// 128(M) x 64(N) CTA, 128 threads, 2x2 warps of 64x32, 3-stage cp.async, 3 CTA/SM.
template <int LAYOUT>
__global__ void __launch_bounds__(128, 3) hmma_gemm(const __half* __restrict__ A,
                                                    const __half* __restrict__ Bx,
                                                    const float* __restrict__ bias,
                                                    float* __restrict__ Out) {
    extern __shared__ char smraw[];
    const uint32_t sbr = s2u(smraw);
    const uint32_t sb = (sbr + 1023u) & ~1023u;
    char* smg = smraw + (sb - sbr);

    const int t = threadIdx.x, lane = t & 31, wid = t >> 5;
    const int b = blockIdx.z, m0 = blockIdx.y * 128, n0 = blockIdx.x * 64;
    const int wm = wid >> 1, wn = wid & 1;          // 2x2 warps, 64x32 each

    const uint32_t sA = sb;              // 3 x 16KB A stage buffers
    const uint32_t sB = sb + 49152;      // 3 x 8KB B stage buffers

    auto load_A = [&](int s, int buf) {
        const __half* asrc = A + (size_t)m0 * 256 + s * 64;
        const uint32_t ab = sA + buf * 16384;
#pragma unroll
        for (int i = 0; i < 8; i++) {
            int u = t + i * 128, row = u >> 3, ch = u & 7;
            uint32_t off = row * 128 + ch * 16;
            cp16(ab + SWZ(off), asrc + (size_t)row * 256 + ch * 8);
        }
    };
    auto load_B = [&](int s, int buf) {
        const __half* bsrc = Bx + ((size_t)(b * Pn + n0)) * 256 + s * 64;
        const uint32_t bb = sB + buf * 8192;
#pragma unroll
        for (int i = 0; i < 4; i++) {
            int u = t + i * 128, row = u >> 3, ch = u & 7;
            uint32_t off = row * 128 + ch * 16;
            cp16(bb + SWZ(off), bsrc + (size_t)row * 256 + ch * 8);
        }
    };

    float acc[4][4][4] = {};

    load_A(0, 0); load_B(0, 0); CP_COMMIT();
    load_A(1, 1); load_B(1, 1); CP_COMMIT();

    for (int s = 0; s < 4; s++) {
        if (s == 3) { CP_WAIT(0); } else { CP_WAIT(1); }
        __syncthreads();
        const uint32_t abase = sA + (s % 3) * 16384;
        const uint32_t bbase = sB + (s % 3) * 8192;
#pragma unroll
        for (int kk = 0; kk < 4; kk++) {
            uint32_t af[4][4], bf[2][4];
#pragma unroll
            for (int mf = 0; mf < 4; mf++) {
                uint32_t off = (uint32_t)(wm * 64 + mf * 16 + (lane & 15)) * 128
                             + kk * 32 + ((lane >> 4) << 4);
                ldsm4(af[mf], abase + SWZ(off));
            }
#pragma unroll
            for (int np = 0; np < 2; np++) {
                uint32_t off = (uint32_t)(wn * 32 + np * 16 + (lane & 7) + ((lane >> 4) << 3)) * 128
                             + kk * 32 + (((lane >> 3) & 1) << 4);
                ldsm4(bf[np], bbase + SWZ(off));
            }
#pragma unroll
            for (int mf = 0; mf < 4; mf++)
#pragma unroll
                for (int nf = 0; nf < 4; nf++)
                    mma16816(acc[mf][nf], af[mf], bf[nf >> 1][(nf & 1) * 2], bf[nf >> 1][(nf & 1) * 2 + 1]);
        }
        if (s + 2 < 4) { load_A(s + 2, (s + 2) % 3); load_B(s + 2, (s + 2) % 3); CP_COMMIT(); }
    }

    if (LAYOUT == 0) {
        __syncthreads();
        float* patch = (float*)smg + wid * (64 * 33);
#pragma unroll
        for (int mf = 0; mf < 4; mf++) {
            const int r0 = mf * 16 + (lane >> 2);
#pragma unroll
            for (int nf = 0; nf < 4; nf++) {
                const int cb = nf * 8 + 2 * (lane & 3);
                patch[r0 * 33 + cb]           = acc[mf][nf][0];
                patch[r0 * 33 + cb + 1]       = acc[mf][nf][1];
                patch[(r0 + 8) * 33 + cb]     = acc[mf][nf][2];
                patch[(r0 + 8) * 33 + cb + 1] = acc[mf][nf][3];
            }
        }
        __syncwarp();
        const int p = n0 + wn * 32 + lane;
#pragma unroll
        for (int q = 0; q < 16; q++) {
            const int mg = m0 + wm * 64 + q * 4;
            float4 v = make_float4(patch[(q * 4 + 0) * 33 + lane] + bias[mg],
                                   patch[(q * 4 + 1) * 33 + lane] + bias[mg + 1],
                                   patch[(q * 4 + 2) * 33 + lane] + bias[mg + 2],
                                   patch[(q * 4 + 3) * 33 + lane] + bias[mg + 3]);
            const int g = mg >> 5, dq = (mg & 31) >> 2;
            *(float4*)(Out + (((size_t)(b * 24 + g) * 8 + dq) * Pn + p) * 4) = v;
        }
    } else {
#pragma unroll
        for (int mf = 0; mf < 4; mf++) {
            const int r0 = m0 + wm * 64 + mf * 16 + (lane >> 2);
            const float b0v = bias[r0], b1v = bias[r0 + 8];
#pragma unroll
            for (int nf = 0; nf < 4; nf++) {
                const int cc = n0 + wn * 32 + nf * 8 + 2 * (lane & 3);
                float2 v0 = make_float2(acc[mf][nf][0] + b0v, acc[mf][nf][1] + b0v);
                *(float2*)(Out + ((size_t)b * 256 + r0) * Pn + cc) = v0;
                float2 v1 = make_float2(acc[mf][nf][2] + b1v, acc[mf][nf][3] + b1v);
                *(float2*)(Out + ((size_t)b * 256 + r0 + 8) * Pn + cc) = v1;
            }
        }
    }
}

// ---------------- warp-cooperative attention (R11; single fp16 output) ----------------
__global__ void __launch_bounds__(128) attn_kernel() {
    const int bh = blockIdx.y;
    const int b  = bh >> 3;
    const int hd = bh & 7;
    const int lane = threadIdx.x & 31, warp = threadIdx.x >> 5;
    const int plocal = lane & 7, sub = lane >> 3;
    const int p  = blockIdx.x * 32 + warp * 8 + plocal;
    const int h  = p >> 6;
    const int w  = p & 63;
    const int dil = (hd & 3) + 1;

    const float* qb = g_qkv + ((size_t)((b * 24 + 0 * 8 + hd) * 8)) * Pn * 4;
    const float* kb = g_qkv + ((size_t)((b * 24 + 1 * 8 + hd) * 8)) * Pn * 4;
    const float* vb = g_qkv + ((size_t)((b * 24 + 2 * 8 + hd) * 8)) * Pn * 4;

    const int dq0 = 2 * sub, dq1 = 2 * sub + 1;
    const float4 q0 = *(const float4*)(qb + ((size_t)dq0 * Pn + p) * 4);
    const float4 q1 = *(const float4*)(qb + ((size_t)dq1 * Pn + p) * 4);

    float s[9];
    int   np[9];
#pragma unroll
    for (int dy = 0; dy < 3; dy++) {
#pragma unroll
        for (int dx = 0; dx < 3; dx++) {
            const int j  = dy * 3 + dx;
            const int hh = h + (dy - 1) * dil;
            const int ww = w + (dx - 1) * dil;
            const bool valid = (hh >= 0 && hh < Hn && ww >= 0 && ww < Wn);
            const int pn = valid ? (hh * Wn + ww) : p;
            float4 k0 = *(const float4*)(kb + ((size_t)dq0 * Pn + pn) * 4);
            float4 k1 = *(const float4*)(kb + ((size_t)dq1 * Pn + pn) * 4);
            float part = q0.x * k0.x + q0.y * k0.y + q0.z * k0.z + q0.w * k0.w
                       + q1.x * k1.x + q1.y * k1.y + q1.z * k1.z + q1.w * k1.w;
            part += __shfl_xor_sync(0xFFFFFFFFu, part, 8);
            part += __shfl_xor_sync(0xFFFFFFFFu, part, 16);
            s[j]  = valid ? part * SCALEF : 0.f;
            np[j] = valid ? pn : -1;
        }
    }

    float mx = s[0];
#pragma unroll
    for (int j = 1; j < 9; j++) mx = fmaxf(mx, s[j]);
    float e[9];
    float sum = 0.f;
#pragma unroll
    for (int j = 0; j < 9; j++) { e[j] = __expf(s[j] - mx); sum += e[j]; }
    const float inv = 1.f / sum;

    float o0x = 0.f, o0y = 0.f, o0z = 0.f, o0w = 0.f;
    float o1x = 0.f, o1y = 0.f, o1z = 0.f, o1w = 0.f;
#pragma unroll
    for (int j = 0; j < 9; j++) {
        if (np[j] >= 0) {
            const float ej = e[j];
            float4 v0 = *(const float4*)(vb + ((size_t)dq0 * Pn + np[j]) * 4);
            float4 v1 = *(const float4*)(vb + ((size_t)dq1 * Pn + np[j]) * 4);
            o0x += ej * v0.x; o0y += ej * v0.y; o0z += ej * v0.z; o0w += ej * v0.w;
            o1x += ej * v1.x; o1y += ej * v1.y; o1z += ej * v1.z; o1w += ej * v1.w;
        }
    }
    o0x *= inv; o0y *= inv; o0z *= inv; o0w *= inv;
    o1x *= inv; o1y *= inv; o1z *= inv; o1w *= inv;

    // pack 8 fp32 -> 4 half2 = 16B, one store
    __half2 h0 = __floats2half2_rn(o0x, o0y);
    __half2 h1 = __floats2half2_rn(o0z, o0w);
    __half2 h2 = __floats2half2_rn(o1x, o1y);
    __half2 h3 = __floats2half2_rn(o1z, o1w);
    const size_t co = ((size_t)(b * Pn + p)) * 256 + hd * 32 + sub * 8;
    *(uint4*)(g_a + co) = make_uint4(*(uint32_t*)&h0, *(uint32_t*)&h1,
                                     *(uint32_t*)&h2, *(uint32_t*)&h3);
}

// ---------------------------------------------------------------------------
extern "C" void kernel_launch(void* const* d_in, const int* in_sizes, int n_in,
                              void* d_out, int out_size) {
    const float* x      = (const float*)d_in[0];
    const float* w_qkv  = (const float*)d_in[1];
    const float* b_qkv  = (const float*)d_in[2];
    const float* w_proj = (const float*)d_in[3];
    const float* b_proj = (const float*)d_in[4];
    float* out = (float*)d_out;

    float* qkvp = nullptr;
    __half *w1p = nullptr, *w2p = nullptr, *xp = nullptr, *ap = nullptr;
    cudaGetSymbolAddress((void**)&qkvp, g_qkv);
    cudaGetSymbolAddress((void**)&w1p, g_w1);
    cudaGetSymbolAddress((void**)&w2p, g_w2);
    cudaGetSymbolAddress((void**)&xp, g_x);
    cudaGetSymbolAddress((void**)&ap, g_a);

    const int SMEM_BYTES = 1024 + 49152 + 24576;   // pad + 3x16KB A + 3x8KB B
    cudaFuncSetAttribute(hmma_gemm<0>, cudaFuncAttributeMaxDynamicSharedMemorySize, SMEM_BYTES);
    cudaFuncSetAttribute(hmma_gemm<1>, cudaFuncAttributeMaxDynamicSharedMemorySize, SMEM_BYTES);

    prep_w1<<<(768 * 256 + 255) / 256, 256>>>(w_qkv);
    prep_w2<<<(256 * 256 + 255) / 256, 256>>>(w_proj);
    conv_split<<<dim3(Pn / 32, Cn / 32, Bn), dim3(32, 8)>>>(x, xp);
    hmma_gemm<0><<<dim3(Pn / 64, 768 / 128, Bn), 128, SMEM_BYTES>>>(w1p, xp, b_qkv, qkvp);
    attn_kernel<<<dim3(Pn / 32, Bn * 8), 128>>>();
    hmma_gemm<1><<<dim3(Pn / 64, 256 / 128, Bn), 128, SMEM_BYTES>>>(w2p, ap, b_proj, out);
}

// round 17
// speedup vs baseline: 1.8945x; 1.0759x over previous
#include <cuda_runtime.h>
#include <cuda_fp16.h>
#include <stdint.h>
#include <math.h>

#define Bn   8
#define Cn   256
#define Hn   64
#define Wn   64
#define Pn   4096
#define SCALEF 0.1767766952966369f

// qkv fp16, octet layout: [b][g=s*8+hd :24][do:4][p:4096][8 halfs]
__device__ __half g_qkv16[(size_t)Bn * 24 * 4 * Pn * 8];   // ~50 MB
__device__ __half g_w1[768 * 256];                 // fp16 weights, K=256
__device__ __half g_w2[256 * 256];
__device__ __half g_x[(size_t)Bn * Pn * Cn];       // [b][p][c] fp16
__device__ __half g_a[(size_t)Bn * Pn * Cn];

// ---------------- helpers ----------------
__device__ __forceinline__ uint32_t s2u(const void* p) {
    uint32_t a;
    asm("{ .reg .u64 t; cvta.to.shared.u64 t, %1; cvt.u32.u64 %0, t; }" : "=r"(a) : "l"(p));
    return a;
}
__device__ __forceinline__ void cp16(uint32_t dst, const void* src) {
    asm volatile("cp.async.cg.shared.global [%0], [%1], 16;" :: "r"(dst), "l"(src));
}
#define CP_COMMIT() asm volatile("cp.async.commit_group;" ::: "memory")
#define CP_WAIT(n)  asm volatile("cp.async.wait_group %0;" :: "n"(n) : "memory")
#define SWZ(o) ((o) ^ (((o) >> 3) & 0x70))

__device__ __forceinline__ void ldsm4(uint32_t* r, uint32_t a) {
    asm volatile("ldmatrix.sync.aligned.m8n8.x4.shared.b16 {%0,%1,%2,%3}, [%4];"
                 : "=r"(r[0]), "=r"(r[1]), "=r"(r[2]), "=r"(r[3]) : "r"(a));
}
// f16 inputs, f32 accumulate
__device__ __forceinline__ void mma16816(float* c, const uint32_t* a, uint32_t b0, uint32_t b1) {
    asm volatile("mma.sync.aligned.m16n8k16.row.col.f32.f16.f16.f32 "
                 "{%0,%1,%2,%3},{%4,%5,%6,%7},{%8,%9},{%0,%1,%2,%3};"
                 : "+f"(c[0]), "+f"(c[1]), "+f"(c[2]), "+f"(c[3])
                 : "r"(a[0]), "r"(a[1]), "r"(a[2]), "r"(a[3]), "r"(b0), "r"(b1));
}

// ---------------- prep: weights -> fp16 ----------------
__global__ void prep_w1(const float* __restrict__ wq) {
    int idx = blockIdx.x * 256 + threadIdx.x;
    if (idx < 768 * 256) g_w1[idx] = __float2half(wq[idx]);
}
__global__ void prep_w2(const float* __restrict__ wp) {
    int idx = blockIdx.x * 256 + threadIdx.x;
    if (idx < 256 * 256) g_w2[idx] = __float2half(wp[idx]);
}

// -------- transpose: [b][c][p] fp32 -> [b][p][c] fp16 --------
__global__ void conv_split(const float* __restrict__ in, __half* __restrict__ o16) {
    __shared__ float t[32][33];
    const int b = blockIdx.z, c0 = blockIdx.y * 32, p0 = blockIdx.x * 32;
    const int tx = threadIdx.x, ty = threadIdx.y;
    const float* ip = in + ((size_t)b * Cn + c0) * Pn + p0;
#pragma unroll
    for (int r = 0; r < 4; r++)
        t[ty + r * 8][tx] = ip[(size_t)(ty + r * 8) * Pn + tx];
    __syncthreads();
#pragma unroll
    for (int r = 0; r < 4; r++) {
        int pr = ty + r * 8;
        o16[((size_t)b * Pn + p0 + pr) * Cn + c0 + tx] = __float2half(t[tx][pr]);
    }
}

// ---------------- HMMA fp16 GEMM, K=256, 128x128 CTA, 4 warps of 64x64 ----------------
// (R14 shape: minimal LDSM traffic per MMA — the GEMM is L1-bound at K=256.)
// LAYOUT 0: fp16 octet qkv output. LAYOUT 1: fp32 [b][m][p] output.
template <int LAYOUT>
__global__ void __launch_bounds__(128, 2) hmma_gemm(const __half* __restrict__ A,
                                                    const __half* __restrict__ Bx,
                                                    const float* __restrict__ bias,
                                                    __half* __restrict__ Out16,
                                                    float* __restrict__ Out32) {
    extern __shared__ char smraw[];
    const uint32_t sbr = s2u(smraw);
    const uint32_t sb = (sbr + 1023u) & ~1023u;
    char* smg = smraw + (sb - sbr);

    const int t = threadIdx.x, lane = t & 31, wid = t >> 5;
    const int b = blockIdx.z, m0 = blockIdx.y * 128, n0 = blockIdx.x * 128;
    const int wm = wid >> 1, wn = wid & 1;          // 2x2 warps, 64x64 each

    const uint32_t sA = sb;              // 3 x 16KB A stage buffers
    const uint32_t sB = sb + 49152;      // 3 x 16KB B stage buffers

    auto load_A = [&](int s, int buf) {
        const __half* asrc = A + (size_t)m0 * 256 + s * 64;
        const uint32_t ab = sA + buf * 16384;
#pragma unroll
        for (int i = 0; i < 8; i++) {
            int u = t + i * 128, row = u >> 3, ch = u & 7;
            uint32_t off = row * 128 + ch * 16;
            cp16(ab + SWZ(off), asrc + (size_t)row * 256 + ch * 8);
        }
    };
    auto load_B = [&](int s, int buf) {
        const __half* bsrc = Bx + ((size_t)(b * Pn + n0)) * 256 + s * 64;
        const uint32_t bb = sB + buf * 16384;
#pragma unroll
        for (int i = 0; i < 8; i++) {
            int u = t + i * 128, row = u >> 3, ch = u & 7;
            uint32_t off = row * 128 + ch * 16;
            cp16(bb + SWZ(off), bsrc + (size_t)row * 256 + ch * 8);
        }
    };

    float acc[4][8][4] = {};

    load_A(0, 0); load_B(0, 0); CP_COMMIT();
    load_A(1, 1); load_B(1, 1); CP_COMMIT();

    for (int s = 0; s < 4; s++) {
        if (s == 3) { CP_WAIT(0); } else { CP_WAIT(1); }
        __syncthreads();
        const uint32_t abase = sA + (s % 3) * 16384;
        const uint32_t bbase = sB + (s % 3) * 16384;
#pragma unroll
        for (int kk = 0; kk < 4; kk++) {
            uint32_t af[4][4], bf[4][4];
#pragma unroll
            for (int mf = 0; mf < 4; mf++) {
                uint32_t off = (uint32_t)(wm * 64 + mf * 16 + (lane & 15)) * 128
                             + kk * 32 + ((lane >> 4) << 4);
                ldsm4(af[mf], abase + SWZ(off));
            }
#pragma unroll
            for (int np = 0; np < 4; np++) {
                uint32_t off = (uint32_t)(wn * 64 + np * 16 + (lane & 7) + ((lane >> 4) << 3)) * 128
                             + kk * 32 + (((lane >> 3) & 1) << 4);
                ldsm4(bf[np], bbase + SWZ(off));
            }
#pragma unroll
            for (int mf = 0; mf < 4; mf++)
#pragma unroll
                for (int nf = 0; nf < 8; nf++)
                    mma16816(acc[mf][nf], af[mf], bf[nf >> 1][(nf & 1) * 2], bf[nf >> 1][(nf & 1) * 2 + 1]);
        }
        if (s + 2 < 4) { load_A(s + 2, (s + 2) % 3); load_B(s + 2, (s + 2) % 3); CP_COMMIT(); }
    }

    if (LAYOUT == 0) {
        __syncthreads();
        float* patch = (float*)smg + wid * (64 * 33);
#pragma unroll
        for (int pass = 0; pass < 2; pass++) {
#pragma unroll
            for (int mf = 0; mf < 4; mf++) {
                const int r0 = mf * 16 + (lane >> 2);
#pragma unroll
                for (int nl = 0; nl < 4; nl++) {
                    const int nf = pass * 4 + nl;
                    const int cb = nl * 8 + 2 * (lane & 3);
                    patch[r0 * 33 + cb]           = acc[mf][nf][0];
                    patch[r0 * 33 + cb + 1]       = acc[mf][nf][1];
                    patch[(r0 + 8) * 33 + cb]     = acc[mf][nf][2];
                    patch[(r0 + 8) * 33 + cb + 1] = acc[mf][nf][3];
                }
            }
            __syncwarp();
            const int p = n0 + wn * 64 + pass * 32 + lane;
#pragma unroll
            for (int q8 = 0; q8 < 8; q8++) {
                const int mg = m0 + wm * 64 + q8 * 8;
                float f[8];
#pragma unroll
                for (int j = 0; j < 8; j++)
                    f[j] = patch[(q8 * 8 + j) * 33 + lane] + bias[mg + j];
                __half2 h0 = __floats2half2_rn(f[0], f[1]);
                __half2 h1 = __floats2half2_rn(f[2], f[3]);
                __half2 h2 = __floats2half2_rn(f[4], f[5]);
                __half2 h3 = __floats2half2_rn(f[6], f[7]);
                const int g = mg >> 5, doc = (mg & 31) >> 3;
                *(uint4*)(Out16 + (((size_t)(b * 24 + g) * 4 + doc) * Pn + p) * 8) =
                    make_uint4(*(uint32_t*)&h0, *(uint32_t*)&h1,
                               *(uint32_t*)&h2, *(uint32_t*)&h3);
            }
            __syncwarp();
        }
    } else {
#pragma unroll
        for (int mf = 0; mf < 4; mf++) {
            const int r0 = m0 + wm * 64 + mf * 16 + (lane >> 2);
            const float b0v = bias[r0], b1v = bias[r0 + 8];
#pragma unroll
            for (int nf = 0; nf < 8; nf++) {
                const int cc = n0 + wn * 64 + nf * 8 + 2 * (lane & 3);
                float2 v0 = make_float2(acc[mf][nf][0] + b0v, acc[mf][nf][1] + b0v);
                *(float2*)(Out32 + ((size_t)b * 256 + r0) * Pn + cc) = v0;
                float2 v1 = make_float2(acc[mf][nf][2] + b1v, acc[mf][nf][3] + b1v);
                *(float2*)(Out32 + ((size_t)b * 256 + r0 + 8) * Pn + cc) = v1;
            }
        }
    }
}

// ---------------- warp-cooperative attention, fp16 qkv (one 16B load/neighbor) ----------------
__device__ __forceinline__ void h8_to_f8(uint4 raw, float* f) {
    const __half2* h = (const __half2*)&raw;
#pragma unroll
    for (int i = 0; i < 4; i++) {
        float2 v = __half22float2(h[i]);
        f[2 * i] = v.x; f[2 * i + 1] = v.y;
    }
}

__global__ void __launch_bounds__(128) attn_kernel() {
    const int bh = blockIdx.y;
    const int b  = bh >> 3;
    const int hd = bh & 7;
    const int lane = threadIdx.x & 31, warp = threadIdx.x >> 5;
    const int plocal = lane & 7, sub = lane >> 3;
    const int p  = blockIdx.x * 32 + warp * 8 + plocal;
    const int h  = p >> 6;
    const int w  = p & 63;
    const int dil = (hd & 3) + 1;

    const __half* qb = g_qkv16 + ((size_t)((b * 24 + 0 * 8 + hd) * 4)) * Pn * 8;
    const __half* kb = g_qkv16 + ((size_t)((b * 24 + 1 * 8 + hd) * 4)) * Pn * 8;
    const __half* vb = g_qkv16 + ((size_t)((b * 24 + 2 * 8 + hd) * 4)) * Pn * 8;

    float q[8];
    h8_to_f8(*(const uint4*)(qb + ((size_t)sub * Pn + p) * 8), q);

    float s[9];
    int   np[9];
#pragma unroll
    for (int dy = 0; dy < 3; dy++) {
#pragma unroll
        for (int dx = 0; dx < 3; dx++) {
            const int j  = dy * 3 + dx;
            const int hh = h + (dy - 1) * dil;
            const int ww = w + (dx - 1) * dil;
            const bool valid = (hh >= 0 && hh < Hn && ww >= 0 && ww < Wn);
            const int pn = valid ? (hh * Wn + ww) : p;
            float k8[8];
            h8_to_f8(*(const uint4*)(kb + ((size_t)sub * Pn + pn) * 8), k8);
            float part = q[0] * k8[0] + q[1] * k8[1] + q[2] * k8[2] + q[3] * k8[3]
                       + q[4] * k8[4] + q[5] * k8[5] + q[6] * k8[6] + q[7] * k8[7];
            part += __shfl_xor_sync(0xFFFFFFFFu, part, 8);
            part += __shfl_xor_sync(0xFFFFFFFFu, part, 16);
            s[j]  = valid ? part * SCALEF : 0.f;
            np[j] = valid ? pn : -1;
        }
    }

    float mx = s[0];
#pragma unroll
    for (int j = 1; j < 9; j++) mx = fmaxf(mx, s[j]);
    float e[9];
    float sum = 0.f;
#pragma unroll
    for (int j = 0; j < 9; j++) { e[j] = __expf(s[j] - mx); sum += e[j]; }
    const float inv = 1.f / sum;

    float o[8] = {};
#pragma unroll
    for (int j = 0; j < 9; j++) {
        if (np[j] >= 0) {
            const float ej = e[j];
            float v8[8];
            h8_to_f8(*(const uint4*)(vb + ((size_t)sub * Pn + np[j]) * 8), v8);
#pragma unroll
            for (int i = 0; i < 8; i++) o[i] += ej * v8[i];
        }
    }
#pragma unroll
    for (int i = 0; i < 8; i++) o[i] *= inv;

    __half2 h0 = __floats2half2_rn(o[0], o[1]);
    __half2 h1 = __floats2half2_rn(o[2], o[3]);
    __half2 h2 = __floats2half2_rn(o[4], o[5]);
    __half2 h3 = __floats2half2_rn(o[6], o[7]);
    const size_t co = ((size_t)(b * Pn + p)) * 256 + hd * 32 + sub * 8;
    *(uint4*)(g_a + co) = make_uint4(*(uint32_t*)&h0, *(uint32_t*)&h1,
                                     *(uint32_t*)&h2, *(uint32_t*)&h3);
}

// ---------------------------------------------------------------------------
extern "C" void kernel_launch(void* const* d_in, const int* in_sizes, int n_in,
                              void* d_out, int out_size) {
    const float* x      = (const float*)d_in[0];
    const float* w_qkv  = (const float*)d_in[1];
    const float* b_qkv  = (const float*)d_in[2];
    const float* w_proj = (const float*)d_in[3];
    const float* b_proj = (const float*)d_in[4];
    float* out = (float*)d_out;

    __half *qkvp = nullptr, *w1p = nullptr, *w2p = nullptr, *xp = nullptr, *ap = nullptr;
    cudaGetSymbolAddress((void**)&qkvp, g_qkv16);
    cudaGetSymbolAddress((void**)&w1p, g_w1);
    cudaGetSymbolAddress((void**)&w2p, g_w2);
    cudaGetSymbolAddress((void**)&xp, g_x);
    cudaGetSymbolAddress((void**)&ap, g_a);

    const int SMEM_BYTES = 1024 + 49152 + 49152;   // pad + 3x16KB A + 3x16KB B
    cudaFuncSetAttribute(hmma_gemm<0>, cudaFuncAttributeMaxDynamicSharedMemorySize, SMEM_BYTES);
    cudaFuncSetAttribute(hmma_gemm<1>, cudaFuncAttributeMaxDynamicSharedMemorySize, SMEM_BYTES);

    prep_w1<<<(768 * 256 + 255) / 256, 256>>>(w_qkv);
    prep_w2<<<(256 * 256 + 255) / 256, 256>>>(w_proj);
    conv_split<<<dim3(Pn / 32, Cn / 32, Bn), dim3(32, 8)>>>(x, xp);
    hmma_gemm<0><<<dim3(Pn / 128, 768 / 128, Bn), 128, SMEM_BYTES>>>(w1p, xp, b_qkv, qkvp, nullptr);
    attn_kernel<<<dim3(Pn / 32, Bn * 8), 128>>>();
    hmma_gemm<1><<<dim3(Pn / 128, 256 / 128, Bn), 128, SMEM_BYTES>>>(w2p, ap, b_proj, nullptr, out);
}